// round 11
// baseline (speedup 1.0000x reference)
#include <cuda_runtime.h>
#include <cuda_fp16.h>
#include <cstdint>

#define D       64
#define KCW     512
#define NROWS   262144
#define LTILES  512                // logical tiles of 512 rows (2 phys x 256)
#define THREADS 512

#define BSTRIDE  144               // 64 fp16 = 128B + 16B pad
#define CB_OFF   0                 // 512*144 = 73728
#define HCSQ_OFF 73728             // +2048 -> 75776
#define XSTG_OFF 75776             // fp32 staging 256*256 = 65536 -> 141312
#define A0_OFF   141312            // fp16 tile 256*144 = 36864 -> 178176
#define A1_OFF   178176            // -> 215040
#define XSQ0_OFF 215040            // 1024 -> 216064
#define XSQ1_OFF 216064            // 1024 -> 217088
#define MB_OFF   217088
#define SM_TOTAL 217344
#define THRESH   0.08f
#define FINF     3.402823466e38f
#define PINF     __int_as_float(0x7f800000)

__device__ float g_partial[256];
__device__ int   g_counter;

// ---------------- helpers ----------------
__device__ __forceinline__ uint32_t smem_u32(const void* p) {
    uint32_t a;
    asm("{ .reg .u64 t; cvta.to.shared.u64 t, %1; cvt.u32.u64 %0, t; }" : "=r"(a) : "l"(p));
    return a;
}
__device__ __forceinline__ void mbar_init(uint32_t a, uint32_t cnt) {
    asm volatile("mbarrier.init.shared.b64 [%0], %1;" :: "r"(a), "r"(cnt) : "memory");
}
__device__ __forceinline__ void mbar_expect_tx(uint32_t a, uint32_t bytes) {
    asm volatile("mbarrier.arrive.expect_tx.shared.b64 _, [%0], %1;" :: "r"(a), "r"(bytes) : "memory");
}
__device__ __forceinline__ void bulk_g2s(uint32_t dst, const void* src, uint32_t bytes, uint32_t mbar) {
    asm volatile("cp.async.bulk.shared::cluster.global.mbarrier::complete_tx::bytes [%0], [%1], %2, [%3];"
                 :: "r"(dst), "l"(src), "r"(bytes), "r"(mbar) : "memory");
}
__device__ __forceinline__ void bar_wait(uint32_t a, uint32_t parity) {
    asm volatile(
        "{\n\t.reg .pred P;\n"
        "W%=:\n\t"
        "mbarrier.try_wait.parity.acquire.cta.shared::cta.b64 P, [%0], %1, 0x989680;\n\t"
        "@P bra DONE%=;\n\t"
        "bra W%=;\n"
        "DONE%=:\n\t}"
        :: "r"(a), "r"(parity) : "memory");
}
__device__ __forceinline__ void mma_f16(float* c, const uint32_t* a, uint32_t b0, uint32_t b1) {
    asm volatile("mma.sync.aligned.m16n8k16.row.col.f32.f16.f16.f32 "
                 "{%0,%1,%2,%3}, {%4,%5,%6,%7}, {%8,%9}, {%0,%1,%2,%3};"
                 : "+f"(c[0]), "+f"(c[1]), "+f"(c[2]), "+f"(c[3])
                 : "r"(a[0]), "r"(a[1]), "r"(a[2]), "r"(a[3]), "r"(b0), "r"(b1));
}
__device__ __forceinline__ void mma_f16_z(float* c, const uint32_t* a, uint32_t b0, uint32_t b1) {
    asm volatile("mma.sync.aligned.m16n8k16.row.col.f32.f16.f16.f32 "
                 "{%0,%1,%2,%3}, {%4,%5,%6,%7}, {%8,%9}, {%10,%10,%10,%10};"
                 : "=f"(c[0]), "=f"(c[1]), "=f"(c[2]), "=f"(c[3])
                 : "r"(a[0]), "r"(a[1]), "r"(a[2]), "r"(a[3]), "r"(b0), "r"(b1), "f"(0.0f));
}
__device__ __forceinline__ void ldsm_x4(uint32_t* r, uint32_t addr) {
    asm volatile("ldmatrix.sync.aligned.m8n8.x4.shared.b16 {%0,%1,%2,%3}, [%4];"
                 : "=r"(r[0]), "=r"(r[1]), "=r"(r[2]), "=r"(r[3]) : "r"(addr));
}
__device__ __forceinline__ uint32_t h2bits(float a, float b) {
    __half2 h = __floats2half2_rn(a, b);
    return *reinterpret_cast<uint32_t*>(&h);
}
__device__ __forceinline__ void ins2(float v, uint32_t col, float& s1, float& s2) {
    float pf = __uint_as_float((__float_as_uint(v) & 0xFFFFFE00u) | col);
    float mx = fmaxf(s1, pf);
    s1 = fminf(s1, pf);
    s2 = fminf(s2, mx);
}
__device__ __forceinline__ void ins4f(float v, float& t1, float& t2, float& t3, float& t4) {
    if (v < t4) {
        if (v < t3) {
            if (v < t2) {
                if (v < t1) { t4 = t3; t3 = t2; t2 = t1; t1 = v; }
                else        { t4 = t3; t3 = t2; t2 = v; }
            } else          { t4 = t3; t3 = v; }
        } else              { t4 = v; }
    }
}

// ---------------- single persistent kernel ----------------
__global__ __launch_bounds__(THREADS, 1) void vq_main_kernel(
    const float* __restrict__ inputs,
    const float* __restrict__ cwf,
    float* __restrict__ out,
    int grid)
{
    extern __shared__ char sm[];
    const uint32_t sb = smem_u32(sm);
    const int tid = threadIdx.x, wid = tid >> 5, lane = tid & 31;
    const int g = lane >> 2, q = lane & 3;

    if (tid == 0) mbar_init(sb + MB_OFF, 1);
    __syncthreads();
    if (tid == 0) {
        mbar_expect_tx(sb + MB_OFF, 256 * D * 4);
        bulk_g2s(sb + XSTG_OFF, inputs + (size_t)(2 * blockIdx.x) * 256 * D, 256 * D * 4, sb + MB_OFF);
    }

    // ---- codebook: fp32 gmem -> fp16 smem rows + 0.5*||c||^2 ----
    {
        float* hcs = reinterpret_cast<float*>(sm + HCSQ_OFF);
        for (int r = tid; r < KCW; r += THREADS) {
            const float4* src = reinterpret_cast<const float4*>(cwf + (size_t)r * D);
            char* dst = sm + CB_OFF + r * BSTRIDE;
            float ssum = 0.f;
            #pragma unroll
            for (int j = 0; j < 8; j++) {
                float4 v0 = src[2 * j], v1 = src[2 * j + 1];
                ssum += v0.x * v0.x + v0.y * v0.y + v0.z * v0.z + v0.w * v0.w
                      + v1.x * v1.x + v1.y * v1.y + v1.z * v1.z + v1.w * v1.w;
                uint4 w;
                w.x = h2bits(v0.x, v0.y); w.y = h2bits(v0.z, v0.w);
                w.z = h2bits(v1.x, v1.y); w.w = h2bits(v1.z, v1.w);
                *reinterpret_cast<uint4*>(dst + j * 16) = w;
            }
            hcs[r] = 0.5f * ssum;
        }
    }

    // ldsm bases
    const uint32_t Bb = sb + CB_OFF
        + (uint32_t)(((lane >> 4) * 8 + (lane & 7)) * BSTRIDE + ((lane >> 3) & 1) * 16);
    const uint32_t Aro = (uint32_t)(((lane & 7) + ((lane >> 3) & 1) * 8) * BSTRIDE + (lane >> 4) * 16);

    uint32_t phase = 0;
    float lacc = 0.0f;
    for (int l = blockIdx.x; l < LTILES; l += grid) {
        // ---- two physical 256-row tiles: wait TMA, convert to A0/A1 ----
        #pragma unroll
        for (int s = 0; s < 2; s++) {
            bar_wait(sb + MB_OFF, phase); phase ^= 1;
            const uint32_t Aoff = s ? A1_OFF : A0_OFF;
            {
                const int r = tid >> 1, h = tid & 1;
                const char* srow = sm + XSTG_OFF + r * 256 + h * 128;
                char* drow = sm + Aoff + r * BSTRIDE + h * 64;
                float* xqb = reinterpret_cast<float*>(sm + (s ? XSQ1_OFF : XSQ0_OFF));
                float ssum = 0.f;
                #pragma unroll
                for (int jj = 0; jj < 8; jj++) {
                    int c = (jj + r) & 7;
                    float4 v = *reinterpret_cast<const float4*>(srow + c * 16);
                    ssum += v.x * v.x + v.y * v.y + v.z * v.z + v.w * v.w;
                    uint2 w;
                    w.x = h2bits(v.x, v.y); w.y = h2bits(v.z, v.w);
                    *reinterpret_cast<uint2*>(drow + c * 8) = w;
                }
                ssum += __shfl_xor_sync(0xffffffffu, ssum, 1);
                if (h == 0) xqb[r] = ssum;
            }
            __syncthreads();     // staging free; A[s] ready
            if (tid == 0) {
                if (s == 0) {
                    mbar_expect_tx(sb + MB_OFF, 256 * D * 4);
                    bulk_g2s(sb + XSTG_OFF, inputs + (size_t)(2 * l + 1) * 256 * D, 256 * D * 4, sb + MB_OFF);
                } else if (l + grid < LTILES) {
                    mbar_expect_tx(sb + MB_OFF, 256 * D * 4);
                    bulk_g2s(sb + XSTG_OFF, inputs + (size_t)(2 * (l + grid)) * 256 * D, 256 * D * 4, sb + MB_OFF);
                }
            }
        }

        // ---- A fragments: 2 sets x 16 rows/warp ----
        uint32_t a[2][4][4];
        {
            #pragma unroll
            for (int s = 0; s < 2; s++) {
                const uint32_t abase = sb + (s ? A1_OFF : A0_OFF) + (uint32_t)(wid * 16) * BSTRIDE + Aro;
                #pragma unroll
                for (int ks = 0; ks < 4; ks++) ldsm_x4(a[s][ks], abase + ks * 32);
            }
        }
        // preload this lane's xsq (row-group rg == q) before the barrier
        float myxsq;
        {
            const int set = q >> 1, half = q & 1;
            myxsq = reinterpret_cast<const float*>(sm + (set ? XSQ1_OFF : XSQ0_OFF))[wid * 16 + half * 8 + g];
        }
        __syncthreads();         // frags+xsq in regs -> A/XSQ buffers reusable next iter

        float s1[4], s2[4];
        #pragma unroll
        for (int i = 0; i < 4; i++) { s1[i] = PINF; s2[i] = PINF; }

        // ---- mainloop: 32 chunks of 16 codewords, B double-buffered in regs ----
        uint32_t bbuf[2][4][4];
        #pragma unroll
        for (int ks = 0; ks < 4; ks++) ldsm_x4(bbuf[0][ks], Bb + ks * 32);

        #pragma unroll 2
        for (int cn = 0; cn < 32; cn++) {
            const int cur = cn & 1, nxt = cur ^ 1;
            if (cn < 31) {                      // prefetch next chunk's B
                const uint32_t bc = Bb + (uint32_t)(cn + 1) * (16 * BSTRIDE);
                #pragma unroll
                for (int ks = 0; ks < 4; ks++) ldsm_x4(bbuf[nxt][ks], bc + ks * 32);
            }

            float acc[2][2][4];                 // [set][octet][reg]
            #pragma unroll
            for (int s = 0; s < 2; s++) {
                mma_f16_z(acc[s][0], a[s][0], bbuf[cur][0][0], bbuf[cur][0][1]);
                mma_f16_z(acc[s][1], a[s][0], bbuf[cur][0][2], bbuf[cur][0][3]);
            }
            #pragma unroll
            for (int ks = 1; ks < 4; ks++)
                #pragma unroll
                for (int s = 0; s < 2; s++) {
                    mma_f16(acc[s][0], a[s][ks], bbuf[cur][ks][0], bbuf[cur][ks][1]);
                    mma_f16(acc[s][1], a[s][ks], bbuf[cur][ks][2], bbuf[cur][ks][3]);
                }

            // epilogue: score = 0.5||c||^2 - x.c ; packed-float top-2 per row-group
            #pragma unroll
            for (int o = 0; o < 2; o++) {
                float2 hc = *reinterpret_cast<const float2*>(sm + HCSQ_OFF + cn * 64 + o * 32 + q * 8);
                uint32_t col = (uint32_t)(cn * 16 + o * 8 + 2 * q);
                #pragma unroll
                for (int s = 0; s < 2; s++) {
                    ins2(hc.x - acc[s][o][0], col,     s1[s * 2],     s2[s * 2]);
                    ins2(hc.y - acc[s][o][1], col + 1, s1[s * 2],     s2[s * 2]);
                    ins2(hc.x - acc[s][o][2], col,     s1[s * 2 + 1], s2[s * 2 + 1]);
                    ins2(hc.y - acc[s][o][3], col + 1, s1[s * 2 + 1], s2[s * 2 + 1]);
                }
            }
        }

        // ---- quad merge each of 4 row-groups into top-4; lane q==rg keeps it ----
        float m1 = PINF, m2 = PINF, m3 = PINF, m4 = PINF;
        #pragma unroll
        for (int rg = 0; rg < 4; rg++) {
            float t1 = s1[rg], t2 = s2[rg], t3 = PINF, t4 = PINF;
            #pragma unroll
            for (int off = 1; off <= 2; off <<= 1) {
                float o1 = __shfl_xor_sync(0xffffffffu, t1, off);
                float o2 = __shfl_xor_sync(0xffffffffu, t2, off);
                float o3 = __shfl_xor_sync(0xffffffffu, t3, off);
                float o4 = __shfl_xor_sync(0xffffffffu, t4, off);
                ins4f(o1, t1, t2, t3, t4);
                ins4f(o2, t1, t2, t3, t4);
                ins4f(o3, t1, t2, t3, t4);
                ins4f(o4, t1, t2, t3, t4);
            }
            if (q == rg) { m1 = t1; m2 = t2; m3 = t3; m4 = t4; }
        }

        // ---- finalize: every lane owns one row (rg == q) ----
        int bidx = 0;
        {
            const int set = q >> 1, half = q & 1;
            const int myrow = (2 * l + set) * 256 + wid * 16 + half * 8 + g;
            const uint32_t u1 = __float_as_uint(m1);
            const float f1 = __uint_as_float(u1 & 0xFFFFFE00u);
            const float f2 = __uint_as_float(__float_as_uint(m2) & 0xFFFFFE00u);
            float dist;
            if (f2 - f1 >= THRESH) {
                bidx = (int)(u1 & 511u);
                dist = fmaf(2.0f, f1, myxsq);
            } else {
                const uint32_t u2 = __float_as_uint(m2), u3 = __float_as_uint(m3), u4 = __float_as_uint(m4);
                float css[4] = {f1, f2,
                                __uint_as_float(u3 & 0xFFFFFE00u),
                                __uint_as_float(u4 & 0xFFFFFE00u)};
                int cjj[4] = {(int)(u1 & 511u), (int)(u2 & 511u), (int)(u3 & 511u), (int)(u4 & 511u)};
                const float4* x4 = reinterpret_cast<const float4*>(inputs + (size_t)myrow * D);
                float bestd = FINF;
                #pragma unroll
                for (int c = 0; c < 4; c++) {
                    if (c < 2 || css[c] - f1 < THRESH) {
                        const float4* c4p = reinterpret_cast<const float4*>(cwf + (size_t)cjj[c] * D);
                        float dd = 0.f;
                        #pragma unroll
                        for (int j = 0; j < 16; j++) {
                            float4 xv = x4[j], cv = c4p[j];
                            float e;
                            e = xv.x - cv.x; dd = fmaf(e, e, dd);
                            e = xv.y - cv.y; dd = fmaf(e, e, dd);
                            e = xv.z - cv.z; dd = fmaf(e, e, dd);
                            e = xv.w - cv.w; dd = fmaf(e, e, dd);
                        }
                        if (dd < bestd || (dd == bestd && cjj[c] < bidx)) { bestd = dd; bidx = cjj[c]; }
                    }
                }
                dist = bestd;
            }
            out[(size_t)NROWS * D + myrow] = (float)bidx;
            lacc += dist;
        }

        // ---- gather winners' exact fp32 codewords (quad-cooperative) ----
        #pragma unroll
        for (int rg = 0; rg < 4; rg++) {
            int w = __shfl_sync(0xffffffffu, bidx, (lane & ~3) + rg);
            const int row = (2 * l + (rg >> 1)) * 256 + wid * 16 + (rg & 1) * 8 + g;
            const float4* c4p = reinterpret_cast<const float4*>(cwf + (size_t)w * D);
            float4* o = reinterpret_cast<float4*>(out + (size_t)row * D);
            #pragma unroll
            for (int j = 0; j < 4; j++) o[j * 4 + q] = c4p[j * 4 + q];
        }
    }

    // ---- loss: block reduce -> partial; last block finalizes ----
    #pragma unroll
    for (int off = 16; off; off >>= 1) lacc += __shfl_xor_sync(0xffffffffu, lacc, off);
    __shared__ float wred[16];
    if (lane == 0) wred[wid] = lacc;
    __syncthreads();
    if (tid == 0) {
        float s = 0.f;
        #pragma unroll
        for (int w = 0; w < 16; w++) s += wred[w];
        g_partial[blockIdx.x] = s;
        __threadfence();
        int ticket = atomicAdd(&g_counter, 1);
        if (ticket == grid - 1) {
            float tot = 0.f;
            for (int i = 0; i < grid; i++) tot += g_partial[i];
            out[(size_t)NROWS * D + NROWS] = 0.25f * tot / (float)((size_t)NROWS * D);
            g_counter = 0;   // reset for next graph replay
        }
    }
}

// ---------------- launch ----------------
extern "C" void kernel_launch(void* const* d_in, const int* in_sizes, int n_in,
                              void* d_out, int out_size) {
    const float* inputs    = (const float*)d_in[0];
    const float* codewords = (const float*)d_in[1];
    float* out = (float*)d_out;

    int sms = 148;
    cudaDeviceGetAttribute(&sms, cudaDevAttrMultiProcessorCount, 0);
    if (sms > 256) sms = 256;

    cudaFuncSetAttribute(vq_main_kernel,
                         cudaFuncAttributeMaxDynamicSharedMemorySize, SM_TOTAL);

    vq_main_kernel<<<sms, THREADS, SM_TOTAL>>>(inputs, codewords, out, sms);
}

// round 12
// speedup vs baseline: 1.5687x; 1.5687x over previous
#include <cuda_runtime.h>
#include <cuda_fp16.h>
#include <cstdint>

#define D       64
#define KCW     512
#define NROWS   262144
#define TILE_M  256
#define NTILES  (NROWS / TILE_M)   // 1024
#define THREADS 512

#define BSTRIDE  144               // 64 fp16 = 128B + 16B pad
#define CB_OFF   0                 // 512*144 = 73728
#define HCSQ_OFF 73728             // +2048 -> 75776
#define XSTG_OFF 75776             // fp32 staging 256*256 = 65536 -> 141312
#define A0_OFF   141312            // fp16 tile 256*144 = 36864 -> 178176
#define A1_OFF   178176            // -> 215040
#define XSQ0_OFF 215040            // 1024 -> 216064
#define XSQ1_OFF 216064            // 1024 -> 217088
#define MB_OFF   217088
#define SM_TOTAL 217344
#define THRESH   0.08f
#define FINF     3.402823466e38f
#define PINF     __int_as_float(0x7f800000)

__device__ float g_partial[256];
__device__ int   g_counter;

// ---------------- helpers ----------------
__device__ __forceinline__ uint32_t smem_u32(const void* p) {
    uint32_t a;
    asm("{ .reg .u64 t; cvta.to.shared.u64 t, %1; cvt.u32.u64 %0, t; }" : "=r"(a) : "l"(p));
    return a;
}
__device__ __forceinline__ void mbar_init(uint32_t a, uint32_t cnt) {
    asm volatile("mbarrier.init.shared.b64 [%0], %1;" :: "r"(a), "r"(cnt) : "memory");
}
__device__ __forceinline__ void mbar_expect_tx(uint32_t a, uint32_t bytes) {
    asm volatile("mbarrier.arrive.expect_tx.shared.b64 _, [%0], %1;" :: "r"(a), "r"(bytes) : "memory");
}
__device__ __forceinline__ void bulk_g2s(uint32_t dst, const void* src, uint32_t bytes, uint32_t mbar) {
    asm volatile("cp.async.bulk.shared::cluster.global.mbarrier::complete_tx::bytes [%0], [%1], %2, [%3];"
                 :: "r"(dst), "l"(src), "r"(bytes), "r"(mbar) : "memory");
}
__device__ __forceinline__ void bar_wait(uint32_t a, uint32_t parity) {
    asm volatile(
        "{\n\t.reg .pred P;\n"
        "W%=:\n\t"
        "mbarrier.try_wait.parity.acquire.cta.shared::cta.b64 P, [%0], %1, 0x989680;\n\t"
        "@P bra DONE%=;\n\t"
        "bra W%=;\n"
        "DONE%=:\n\t}"
        :: "r"(a), "r"(parity) : "memory");
}
__device__ __forceinline__ void mma_f16(float* c, const uint32_t* a, uint32_t b0, uint32_t b1) {
    asm volatile("mma.sync.aligned.m16n8k16.row.col.f32.f16.f16.f32 "
                 "{%0,%1,%2,%3}, {%4,%5,%6,%7}, {%8,%9}, {%0,%1,%2,%3};"
                 : "+f"(c[0]), "+f"(c[1]), "+f"(c[2]), "+f"(c[3])
                 : "r"(a[0]), "r"(a[1]), "r"(a[2]), "r"(a[3]), "r"(b0), "r"(b1));
}
__device__ __forceinline__ void mma_f16_z(float* c, const uint32_t* a, uint32_t b0, uint32_t b1) {
    asm volatile("mma.sync.aligned.m16n8k16.row.col.f32.f16.f16.f32 "
                 "{%0,%1,%2,%3}, {%4,%5,%6,%7}, {%8,%9}, {%10,%10,%10,%10};"
                 : "=f"(c[0]), "=f"(c[1]), "=f"(c[2]), "=f"(c[3])
                 : "r"(a[0]), "r"(a[1]), "r"(a[2]), "r"(a[3]), "r"(b0), "r"(b1), "f"(0.0f));
}
__device__ __forceinline__ void ldsm_x4(uint32_t* r, uint32_t addr) {
    asm volatile("ldmatrix.sync.aligned.m8n8.x4.shared.b16 {%0,%1,%2,%3}, [%4];"
                 : "=r"(r[0]), "=r"(r[1]), "=r"(r[2]), "=r"(r[3]) : "r"(addr));
}
__device__ __forceinline__ uint32_t h2bits(float a, float b) {
    __half2 h = __floats2half2_rn(a, b);
    return *reinterpret_cast<uint32_t*>(&h);
}
__device__ __forceinline__ void ins2(float v, uint32_t col, float& s1, float& s2) {
    float pf = __uint_as_float((__float_as_uint(v) & 0xFFFFFE00u) | col);
    float mx = fmaxf(s1, pf);
    s1 = fminf(s1, pf);
    s2 = fminf(s2, mx);
}
__device__ __forceinline__ void ins4f(float v, float& t1, float& t2, float& t3, float& t4) {
    if (v < t4) {
        if (v < t3) {
            if (v < t2) {
                if (v < t1) { t4 = t3; t3 = t2; t2 = t1; t1 = v; }
                else        { t4 = t3; t3 = t2; t2 = v; }
            } else          { t4 = t3; t3 = v; }
        } else              { t4 = v; }
    }
}

// ---------------- single persistent kernel ----------------
__global__ __launch_bounds__(THREADS, 1) void vq_main_kernel(
    const float* __restrict__ inputs,
    const float* __restrict__ cwf,
    float* __restrict__ out,
    int grid)
{
    extern __shared__ char sm[];
    const uint32_t sb = smem_u32(sm);
    const int tid = threadIdx.x, wid = tid >> 5, lane = tid & 31;
    const int g = lane >> 2, q = lane & 3;

    if (tid == 0) mbar_init(sb + MB_OFF, 1);
    __syncthreads();
    if (tid == 0) {
        mbar_expect_tx(sb + MB_OFF, TILE_M * D * 4);
        bulk_g2s(sb + XSTG_OFF, inputs + (size_t)blockIdx.x * TILE_M * D, TILE_M * D * 4, sb + MB_OFF);
    }

    // ---- codebook: fp32 gmem -> fp16 smem rows + 0.5*||c||^2 ----
    {
        float* hcs = reinterpret_cast<float*>(sm + HCSQ_OFF);
        for (int r = tid; r < KCW; r += THREADS) {
            const float4* src = reinterpret_cast<const float4*>(cwf + (size_t)r * D);
            char* dst = sm + CB_OFF + r * BSTRIDE;
            float ssum = 0.f;
            #pragma unroll
            for (int j = 0; j < 8; j++) {
                float4 v0 = src[2 * j], v1 = src[2 * j + 1];
                ssum += v0.x * v0.x + v0.y * v0.y + v0.z * v0.z + v0.w * v0.w
                      + v1.x * v1.x + v1.y * v1.y + v1.z * v1.z + v1.w * v1.w;
                uint4 w;
                w.x = h2bits(v0.x, v0.y); w.y = h2bits(v0.z, v0.w);
                w.z = h2bits(v1.x, v1.y); w.w = h2bits(v1.z, v1.w);
                *reinterpret_cast<uint4*>(dst + j * 16) = w;
            }
            hcs[r] = 0.5f * ssum;
        }
    }

    // ldsm bases
    const uint32_t Bb = sb + CB_OFF
        + (uint32_t)(((lane >> 4) * 8 + (lane & 7)) * BSTRIDE + ((lane >> 3) & 1) * 16);
    const uint32_t Aro = (uint32_t)(((lane & 7) + ((lane >> 3) & 1) * 8) * BSTRIDE + (lane >> 4) * 16);

    uint32_t phase = 0;
    float lacc = 0.0f;
    int lt = 0;
    for (int t = blockIdx.x; t < NTILES; t += grid, lt++) {
        const int p = lt & 1;
        bar_wait(sb + MB_OFF, phase); phase ^= 1;
        const uint32_t Aoff = p ? A1_OFF : A0_OFF;

        // ---- convert fp32 staging -> fp16 tile + per-row ||x||^2 (2 thr/row) ----
        {
            const int r = tid >> 1, h = tid & 1;
            const char* srow = sm + XSTG_OFF + r * 256 + h * 128;
            char* drow = sm + Aoff + r * BSTRIDE + h * 64;
            float* xqb = reinterpret_cast<float*>(sm + (p ? XSQ1_OFF : XSQ0_OFF));
            float ssum = 0.f;
            #pragma unroll
            for (int jj = 0; jj < 8; jj++) {
                int c = (jj + r) & 7;
                float4 v = *reinterpret_cast<const float4*>(srow + c * 16);
                ssum += v.x * v.x + v.y * v.y + v.z * v.z + v.w * v.w;
                uint2 w;
                w.x = h2bits(v.x, v.y); w.y = h2bits(v.z, v.w);
                *reinterpret_cast<uint2*>(drow + c * 8) = w;
            }
            ssum += __shfl_xor_sync(0xffffffffu, ssum, 1);
            if (h == 0) xqb[r] = ssum;
        }
        __syncthreads();   // tile converted; staging free; codebook visible (iter 0)

        const int tn = t + grid;
        if (tn < NTILES && tid == 0) {
            mbar_expect_tx(sb + MB_OFF, TILE_M * D * 4);
            bulk_g2s(sb + XSTG_OFF, inputs + (size_t)tn * TILE_M * D, TILE_M * D * 4, sb + MB_OFF);
        }

        // ---- A fragments: 16 rows/warp, 4 ks via ldmatrix ----
        uint32_t a[4][4];
        {
            const uint32_t abase = sb + Aoff + (uint32_t)(wid * 16) * BSTRIDE + Aro;
            #pragma unroll
            for (int ks = 0; ks < 4; ks++) ldsm_x4(a[ks], abase + ks * 32);
        }

        float s1g0 = PINF, s2g0 = PINF, s1g1 = PINF, s2g1 = PINF;

        // ---- mainloop: 8 chunks of 64 codewords, B pipelined 1 ldsm deep ----
        uint32_t bb[2][4];
        ldsm_x4(bb[0], Bb);          // (cn=0, ks=0, pr=0)

        #pragma unroll 1
        for (int cn = 0; cn < 8; cn++) {
            float acc[8][4];
            const uint32_t bc = Bb + (uint32_t)cn * (64 * BSTRIDE);
            #pragma unroll
            for (int ks = 0; ks < 4; ks++) {
                #pragma unroll
                for (int pr = 0; pr < 4; pr++) {
                    const int it  = ks * 4 + pr;
                    const int cur = it & 1, nxt = cur ^ 1;
                    // prefetch next iteration's B (last iter: next chunk's head;
                    // cn==7 loads harmlessly past CB into HCSQ/staging region)
                    uint32_t naddr;
                    if (it < 15) {
                        const int nit = it + 1;
                        naddr = bc + (uint32_t)((nit & 3) * (16 * BSTRIDE) + (nit >> 2) * 32);
                    } else {
                        naddr = bc + (uint32_t)(64 * BSTRIDE);
                    }
                    ldsm_x4(bb[nxt], naddr);
                    const int nt = pr * 2;
                    if (ks == 0) {
                        mma_f16_z(acc[nt],     a[ks], bb[cur][0], bb[cur][1]);
                        mma_f16_z(acc[nt + 1], a[ks], bb[cur][2], bb[cur][3]);
                    } else {
                        mma_f16(acc[nt],     a[ks], bb[cur][0], bb[cur][1]);
                        mma_f16(acc[nt + 1], a[ks], bb[cur][2], bb[cur][3]);
                    }
                }
            }
            // epilogue: score = 0.5||c||^2 - x.c ; packed-float top-2 per row-group
            // (runs while the next chunk's head LDSM is in flight)
            #pragma unroll
            for (int nt = 0; nt < 8; nt++) {
                float2 hc = *reinterpret_cast<const float2*>(sm + HCSQ_OFF + cn * 256 + nt * 32 + q * 8);
                uint32_t colA = (uint32_t)(cn * 64 + nt * 8 + 2 * q);
                ins2(hc.x - acc[nt][0], colA,     s1g0, s2g0);
                ins2(hc.y - acc[nt][1], colA + 1, s1g0, s2g0);
                ins2(hc.x - acc[nt][2], colA,     s1g1, s2g1);
                ins2(hc.y - acc[nt][3], colA + 1, s1g1, s2g1);
            }
        }

        // ---- quad merge each row-group into top-4; lane q==rg keeps it ----
        float m1 = PINF, m2 = PINF, m3 = PINF, m4 = PINF;
        #pragma unroll
        for (int rg = 0; rg < 2; rg++) {
            float t1 = rg ? s1g1 : s1g0, t2 = rg ? s2g1 : s2g0, t3 = PINF, t4 = PINF;
            #pragma unroll
            for (int off = 1; off <= 2; off <<= 1) {
                float o1 = __shfl_xor_sync(0xffffffffu, t1, off);
                float o2 = __shfl_xor_sync(0xffffffffu, t2, off);
                float o3 = __shfl_xor_sync(0xffffffffu, t3, off);
                float o4 = __shfl_xor_sync(0xffffffffu, t4, off);
                ins4f(o1, t1, t2, t3, t4);
                ins4f(o2, t1, t2, t3, t4);
                ins4f(o3, t1, t2, t3, t4);
                ins4f(o4, t1, t2, t3, t4);
            }
            if (q == rg) { m1 = t1; m2 = t2; m3 = t3; m4 = t4; }
        }

        const int rowbase = t * TILE_M + wid * 16;

        // ---- finalize (lanes q<2): conditional exact refinement ----
        int bidx = 0;
        if (q < 2) {
            const int myrow = rowbase + q * 8 + g;
            const float xsq = reinterpret_cast<const float*>(sm + (p ? XSQ1_OFF : XSQ0_OFF))[wid * 16 + q * 8 + g];
            const uint32_t u1 = __float_as_uint(m1);
            const float f1 = __uint_as_float(u1 & 0xFFFFFE00u);
            const float f2 = __uint_as_float(__float_as_uint(m2) & 0xFFFFFE00u);
            float dist;
            if (f2 - f1 >= THRESH) {
                bidx = (int)(u1 & 511u);
                dist = fmaf(2.0f, f1, xsq);
            } else {
                const uint32_t u2 = __float_as_uint(m2), u3 = __float_as_uint(m3), u4 = __float_as_uint(m4);
                float css[4] = {f1, f2,
                                __uint_as_float(u3 & 0xFFFFFE00u),
                                __uint_as_float(u4 & 0xFFFFFE00u)};
                int cjj[4] = {(int)(u1 & 511u), (int)(u2 & 511u), (int)(u3 & 511u), (int)(u4 & 511u)};
                const float4* x4 = reinterpret_cast<const float4*>(inputs + (size_t)myrow * D);
                float bestd = FINF;
                #pragma unroll
                for (int c = 0; c < 4; c++) {
                    if (c < 2 || css[c] - f1 < THRESH) {
                        const float4* c4p = reinterpret_cast<const float4*>(cwf + (size_t)cjj[c] * D);
                        float dd = 0.f;
                        #pragma unroll
                        for (int j = 0; j < 16; j++) {
                            float4 xv = x4[j], cv = c4p[j];
                            float e;
                            e = xv.x - cv.x; dd = fmaf(e, e, dd);
                            e = xv.y - cv.y; dd = fmaf(e, e, dd);
                            e = xv.z - cv.z; dd = fmaf(e, e, dd);
                            e = xv.w - cv.w; dd = fmaf(e, e, dd);
                        }
                        if (dd < bestd || (dd == bestd && cjj[c] < bidx)) { bestd = dd; bidx = cjj[c]; }
                    }
                }
                dist = bestd;
            }
            out[(size_t)NROWS * D + myrow] = (float)bidx;
            lacc += dist;
        }

        // ---- gather winners' exact fp32 codewords (quad-cooperative) ----
        #pragma unroll
        for (int rg = 0; rg < 2; rg++) {
            int w = __shfl_sync(0xffffffffu, bidx, (lane & ~3) + rg);
            const int row = rowbase + rg * 8 + g;
            const float4* c4p = reinterpret_cast<const float4*>(cwf + (size_t)w * D);
            float4* o = reinterpret_cast<float4*>(out + (size_t)row * D);
            #pragma unroll
            for (int j = 0; j < 4; j++) o[j * 4 + q] = c4p[j * 4 + q];
        }
    }

    // ---- loss: block reduce -> partial; last block finalizes ----
    #pragma unroll
    for (int off = 16; off; off >>= 1) lacc += __shfl_xor_sync(0xffffffffu, lacc, off);
    __shared__ float wred[16];
    if (lane == 0) wred[wid] = lacc;
    __syncthreads();
    if (tid == 0) {
        float s = 0.f;
        #pragma unroll
        for (int w = 0; w < 16; w++) s += wred[w];
        g_partial[blockIdx.x] = s;
        __threadfence();
        int ticket = atomicAdd(&g_counter, 1);
        if (ticket == grid - 1) {
            float tot = 0.f;
            for (int i = 0; i < grid; i++) tot += g_partial[i];
            out[(size_t)NROWS * D + NROWS] = 0.25f * tot / (float)((size_t)NROWS * D);
            g_counter = 0;   // reset for next graph replay
        }
    }
}

// ---------------- launch ----------------
extern "C" void kernel_launch(void* const* d_in, const int* in_sizes, int n_in,
                              void* d_out, int out_size) {
    const float* inputs    = (const float*)d_in[0];
    const float* codewords = (const float*)d_in[1];
    float* out = (float*)d_out;

    int sms = 148;
    cudaDeviceGetAttribute(&sms, cudaDevAttrMultiProcessorCount, 0);
    if (sms > NTILES) sms = NTILES;
    if (sms > 256)    sms = 256;

    cudaFuncSetAttribute(vq_main_kernel,
                         cudaFuncAttributeMaxDynamicSharedMemorySize, SM_TOTAL);

    vq_main_kernel<<<sms, THREADS, SM_TOTAL>>>(inputs, codewords, out, sms);
}